// round 7
// baseline (speedup 1.0000x reference)
#include <cuda_runtime.h>
#include <math.h>

// x [256, 64, 2048] fp32.
//   xm = max(x, axis=1); gate = softmax(xm, -1)  (SSA groups=1 == identity)
//   out = gate[:, None, :] * x
//
// Single persistent kernel, 148 CTAs (1 per SM, forced by 192KB dynamic SMEM).
// Phase A: stream x, col-maxes -> g_xm; cache first 3 units/CTA in SMEM (~28MB).
// Grid barrier (atomics; all CTAs resident by construction).
// Phase B: softmax g_xm rows in place.
// Phase C: re-read (SMEM for cached, L2 for the rest; non-cached first),
//          scale, __stcs out. DRAM ~= 128MB read + 128MB write.

#define B_   256
#define H_   64
#define N_   2048
#define GRID 148
#define TPB  512
#define TILE 256
#define UNITS (B_ * (N_ / TILE))         // 2048
#define UNIT_FLOATS (H_ * TILE)          // 16384 (64 KB)
#define CACHE_UNITS 3
#define SMEM_BYTES (CACHE_UNITS * UNIT_FLOATS * 4)   // 192 KB

__device__ float g_xm[B_ * N_];
__device__ unsigned g_cnt[2];
__device__ unsigned g_gen[2];

__device__ __forceinline__ void grid_barrier(int slot) {
    __syncthreads();
    if (threadIdx.x == 0) {
        __threadfence();
        unsigned gen = atomicAdd(&g_gen[slot], 0u);   // read current generation
        unsigned old = atomicAdd(&g_cnt[slot], 1u);
        if (old == GRID - 1) {
            g_cnt[slot] = 0;
            __threadfence();
            atomicAdd(&g_gen[slot], 1u);
        } else {
            while (atomicAdd(&g_gen[slot], 0u) == gen) { }
        }
    }
    __syncthreads();
}

__global__ __launch_bounds__(TPB, 1)
void fused_persistent_kernel(const float* __restrict__ x, float* __restrict__ out) {
    extern __shared__ float cache[];       // CACHE_UNITS * 16384 floats
    __shared__ float pmax[8 * TILE];       // 8 KB
    __shared__ float sred[16];
    __shared__ float s_gmax, s_gsum;

    const int cta  = blockIdx.x;
    const int t    = threadIdx.x;
    const int lane = t & 31;
    const int wid  = t >> 5;

    const int col4 = (t & 63) * 4;         // 0..252
    const int hg   = t >> 6;               // 0..7; thread rows h = hg + 8j

    // ================= Phase A: max over h, fill SMEM cache =================
    for (int i = 0, u = cta; u < UNITS; ++i, u += GRID) {
        const int b  = u >> 3;
        const int c0 = (u & 7) * TILE;
        const float* xb = x + (size_t)b * (H_ * N_) + c0;

        float4 v[8];
        #pragma unroll
        for (int j = 0; j < 8; ++j) {
            const int h = hg + j * 8;
            v[j] = *reinterpret_cast<const float4*>(xb + (size_t)h * N_ + col4);
        }
        float4 pm = v[0];
        #pragma unroll
        for (int j = 1; j < 8; ++j) {
            pm.x = fmaxf(pm.x, v[j].x);
            pm.y = fmaxf(pm.y, v[j].y);
            pm.z = fmaxf(pm.z, v[j].z);
            pm.w = fmaxf(pm.w, v[j].w);
        }
        *reinterpret_cast<float4*>(pmax + hg * TILE + col4) = pm;

        if (i < CACHE_UNITS) {
            float* cu = cache + i * UNIT_FLOATS;
            #pragma unroll
            for (int j = 0; j < 8; ++j) {
                const int h = hg + j * 8;
                *reinterpret_cast<float4*>(cu + h * TILE + col4) = v[j];
            }
        }
        __syncthreads();
        if (t < TILE) {
            float m = pmax[t];
            #pragma unroll
            for (int g = 1; g < 8; ++g) m = fmaxf(m, pmax[g * TILE + t]);
            g_xm[(size_t)b * N_ + c0 + t] = m;
        }
        __syncthreads();
    }

    grid_barrier(0);

    // ================= Phase B: softmax rows of g_xm in place ===============
    for (int r = cta; r < B_; r += GRID) {
        float* row = g_xm + (size_t)r * N_;
        float4 v = __ldcg(reinterpret_cast<const float4*>(row + t * 4));

        float tm = fmaxf(fmaxf(v.x, v.y), fmaxf(v.z, v.w));
        #pragma unroll
        for (int o = 16; o > 0; o >>= 1)
            tm = fmaxf(tm, __shfl_xor_sync(0xffffffffu, tm, o));
        if (lane == 0) sred[wid] = tm;
        __syncthreads();
        if (wid == 0) {
            float m = (lane < 16) ? sred[lane] : -INFINITY;
            #pragma unroll
            for (int o = 8; o > 0; o >>= 1)
                m = fmaxf(m, __shfl_xor_sync(0xffffffffu, m, o));
            if (lane == 0) s_gmax = m;
        }
        __syncthreads();
        const float gmax = s_gmax;

        float4 e;
        e.x = expf(v.x - gmax);
        e.y = expf(v.y - gmax);
        e.z = expf(v.z - gmax);
        e.w = expf(v.w - gmax);
        float ts = (e.x + e.y) + (e.z + e.w);
        #pragma unroll
        for (int o = 16; o > 0; o >>= 1)
            ts += __shfl_xor_sync(0xffffffffu, ts, o);
        if (lane == 0) sred[wid] = ts;
        __syncthreads();
        if (wid == 0) {
            float m = (lane < 16) ? sred[lane] : 0.0f;
            #pragma unroll
            for (int o = 8; o > 0; o >>= 1)
                m += __shfl_xor_sync(0xffffffffu, m, o);
            if (lane == 0) s_gsum = m;
        }
        __syncthreads();
        const float inv = 1.0f / s_gsum;

        float4 g = make_float4(e.x * inv, e.y * inv, e.z * inv, e.w * inv);
        *reinterpret_cast<float4*>(row + t * 4) = g;
        __syncthreads();
    }

    grid_barrier(1);

    // ================= Phase C: out = gate * x ==============================
    // Non-cached units first (consume L2 before write evictions), cached last.
    const int rounds = (UNITS - cta + GRID - 1) / GRID;   // 13 or 14
    for (int k = 0; k < rounds; ++k) {
        const int i = (k + CACHE_UNITS < rounds) ? (k + CACHE_UNITS)
                                                 : (k + CACHE_UNITS - rounds);
        const int u  = cta + i * GRID;
        const int b  = u >> 3;
        const int c0 = (u & 7) * TILE;
        const float* xb = x   + (size_t)b * (H_ * N_) + c0;
        float*       ob = out + (size_t)b * (H_ * N_) + c0;

        const float4 g4 = __ldcg(reinterpret_cast<const float4*>(
                              g_xm + (size_t)b * N_ + c0 + col4));

        if (i < CACHE_UNITS) {
            const float* cu = cache + i * UNIT_FLOATS;
            #pragma unroll
            for (int j = 0; j < 8; ++j) {
                const int h = hg + j * 8;
                float4 v = *reinterpret_cast<const float4*>(cu + h * TILE + col4);
                v.x *= g4.x; v.y *= g4.y; v.z *= g4.z; v.w *= g4.w;
                __stcs(reinterpret_cast<float4*>(ob + (size_t)h * N_ + col4), v);
            }
        } else {
            #pragma unroll
            for (int j = 0; j < 8; ++j) {
                const int h = hg + j * 8;
                float4 v = __ldcs(reinterpret_cast<const float4*>(xb + (size_t)h * N_ + col4));
                v.x *= g4.x; v.y *= g4.y; v.z *= g4.z; v.w *= g4.w;
                __stcs(reinterpret_cast<float4*>(ob + (size_t)h * N_ + col4), v);
            }
        }
    }
}

extern "C" void kernel_launch(void* const* d_in, const int* in_sizes, int n_in,
                              void* d_out, int out_size) {
    const float* x = (const float*)d_in[0];
    float* out = (float*)d_out;

    cudaFuncSetAttribute(fused_persistent_kernel,
                         cudaFuncAttributeMaxDynamicSharedMemorySize, SMEM_BYTES);
    fused_persistent_kernel<<<GRID, TPB, SMEM_BYTES>>>(x, out);
}

// round 8
// speedup vs baseline: 1.4070x; 1.4070x over previous
#include <cuda_runtime.h>
#include <math.h>

// x [256, 64, 2048] fp32.
//   xm   = max(x, axis=1); gate = softmax(xm, -1)   (SSA groups=1 == identity)
//   out  = gate[:, None, :] * x
//
// R8: back to decoupled high-occupancy streamers (R6 structure).
//   K1a: partial max over h, 2048 CTAs (74.8% DRAM in R6) -> xm
//   K1b: softmax(xm) in place (tiny)
//   K2 : out = gate*x. Writes use __stwt (write-through: no dirty L2 lines
//        -> x stays L2-resident from K1a's pass). Descending block order
//        (hottest lines first). 4 rows per thread: one gate load per 4 f4.

#define B  256
#define H  64
#define N  2048
#define TILE 256
#define TPB  256

__device__ float g_xm[B * N];    // xm, overwritten in place with gate (2 MB)

// ---- K1a: xm[b, tile] = max over h of x[b, :, tile] ----
__global__ __launch_bounds__(TPB)
void max_kernel(const float* __restrict__ x, float* __restrict__ xm) {
    __shared__ float pmax[4 * TILE];

    const int tileId = blockIdx.x;           // 0..2047
    const int b      = tileId >> 3;
    const int c0     = (tileId & 7) * TILE;
    const int t      = threadIdx.x;

    const float* xb = x + (size_t)b * (H * N) + c0;
    const int c4 = (t & 63) * 4;
    const int h0 = t >> 6;                   // 0..3

    float4 pm = make_float4(-INFINITY, -INFINITY, -INFINITY, -INFINITY);
    #pragma unroll
    for (int it = 0; it < 16; ++it) {
        const int h = h0 + it * 4;
        float4 v = *reinterpret_cast<const float4*>(xb + (size_t)h * N + c4);
        pm.x = fmaxf(pm.x, v.x);
        pm.y = fmaxf(pm.y, v.y);
        pm.z = fmaxf(pm.z, v.z);
        pm.w = fmaxf(pm.w, v.w);
    }
    *reinterpret_cast<float4*>(pmax + h0 * TILE + c4) = pm;
    __syncthreads();

    float m = fmaxf(fmaxf(pmax[0 * TILE + t], pmax[1 * TILE + t]),
                    fmaxf(pmax[2 * TILE + t], pmax[3 * TILE + t]));
    xm[(size_t)b * N + c0 + t] = m;
}

// ---- K1b: gate = softmax(xm) rowwise, in place ----
__global__ __launch_bounds__(512)
void softmax_kernel(float* __restrict__ xm) {
    const int b    = blockIdx.x;
    const int t    = threadIdx.x;
    const int lane = t & 31;
    const int wid  = t >> 5;

    float* row = xm + (size_t)b * N;
    float4 v = *reinterpret_cast<float4*>(row + t * 4);

    __shared__ float sred[16];
    __shared__ float s_gmax, s_gsum;

    float tm = fmaxf(fmaxf(v.x, v.y), fmaxf(v.z, v.w));
    #pragma unroll
    for (int o = 16; o > 0; o >>= 1)
        tm = fmaxf(tm, __shfl_xor_sync(0xffffffffu, tm, o));
    if (lane == 0) sred[wid] = tm;
    __syncthreads();
    if (wid == 0) {
        float m = (lane < 16) ? sred[lane] : -INFINITY;
        #pragma unroll
        for (int o = 8; o > 0; o >>= 1)
            m = fmaxf(m, __shfl_xor_sync(0xffffffffu, m, o));
        if (lane == 0) s_gmax = m;
    }
    __syncthreads();
    const float gmax = s_gmax;

    float4 e;
    e.x = expf(v.x - gmax);
    e.y = expf(v.y - gmax);
    e.z = expf(v.z - gmax);
    e.w = expf(v.w - gmax);
    float ts = (e.x + e.y) + (e.z + e.w);
    #pragma unroll
    for (int o = 16; o > 0; o >>= 1)
        ts += __shfl_xor_sync(0xffffffffu, ts, o);
    if (lane == 0) sred[wid] = ts;
    __syncthreads();
    if (wid == 0) {
        float m = (lane < 16) ? sred[lane] : 0.0f;
        #pragma unroll
        for (int o = 8; o > 0; o >>= 1)
            m += __shfl_xor_sync(0xffffffffu, m, o);
        if (lane == 0) s_gsum = m;
    }
    __syncthreads();
    const float inv = 1.0f / s_gsum;

    float4 g = make_float4(e.x * inv, e.y * inv, e.z * inv, e.w * inv);
    *reinterpret_cast<float4*>(row + t * 4) = g;
}

// ---- K2: out = gate * x ----
// Block owns 4 consecutive h-rows of one batch (8192 floats). Thread t owns
// float4 column t across those 4 rows -> one gate float4 per 4 scales.
// Descending block order; __stwt stores (write-through, no L2 pollution).
#define K2_BLOCKS 4096   // (256*64*2048) / 8192
__global__ __launch_bounds__(512)
void scale_kernel(const float* __restrict__ x, const float* __restrict__ gate,
                  float* __restrict__ out) {
    const long long blk = (long long)(K2_BLOCKS - 1 - blockIdx.x);
    const long long e0  = blk * 8192;           // first element of 4-row group
    const long long b   = e0 >> 17;             // batch
    const int t = threadIdx.x;
    const int n = t * 4;                        // column within row

    const float4 g = *reinterpret_cast<const float4*>(gate + (b << 11) + n);

    const float* xr = x   + e0 + n;
    float*       orr= out + e0 + n;

    float4 v0 = __ldcs(reinterpret_cast<const float4*>(xr + 0 * N));
    float4 v1 = __ldcs(reinterpret_cast<const float4*>(xr + 1 * N));
    float4 v2 = __ldcs(reinterpret_cast<const float4*>(xr + 2 * N));
    float4 v3 = __ldcs(reinterpret_cast<const float4*>(xr + 3 * N));

    v0.x *= g.x; v0.y *= g.y; v0.z *= g.z; v0.w *= g.w;
    v1.x *= g.x; v1.y *= g.y; v1.z *= g.z; v1.w *= g.w;
    v2.x *= g.x; v2.y *= g.y; v2.z *= g.z; v2.w *= g.w;
    v3.x *= g.x; v3.y *= g.y; v3.z *= g.z; v3.w *= g.w;

    __stwt(reinterpret_cast<float4*>(orr + 0 * N), v0);
    __stwt(reinterpret_cast<float4*>(orr + 1 * N), v1);
    __stwt(reinterpret_cast<float4*>(orr + 2 * N), v2);
    __stwt(reinterpret_cast<float4*>(orr + 3 * N), v3);
}

extern "C" void kernel_launch(void* const* d_in, const int* in_sizes, int n_in,
                              void* d_out, int out_size) {
    const float* x = (const float*)d_in[0];
    float* out = (float*)d_out;

    float* xm;
    cudaGetSymbolAddress((void**)&xm, g_xm);

    max_kernel<<<B * (N / TILE), TPB>>>(x, xm);      // 2048 CTAs
    softmax_kernel<<<B, 512>>>(xm);                  // 256 CTAs
    scale_kernel<<<K2_BLOCKS, 512>>>(x, xm, out);    // 4096 CTAs, descending
}

// round 9
// speedup vs baseline: 1.4531x; 1.0328x over previous
#include <cuda_runtime.h>
#include <math.h>

// x [256, 64, 2048] fp32.
//   xm   = max(x, axis=1); gate = softmax(xm, -1)   (SSA groups=1 == identity)
//   out  = gate[:, None, :] * x
//
// R9: per-batch dataflow decoupling. 2048 CTAs x 256 thr (the proven
// high-occupancy shape). Each CTA owns one [64,256] unit: phase A col-max ->
// g_xm; 8th CTA of the batch to arrive computes that row's softmax and raises
// a flag; all 8 then re-read their unit (short reuse distance -> L2 hits),
// scale, __stcs out. No grid barriers, no clusters, no SMEM caching.

#define B  256
#define H  64
#define N  2048
#define TILE 256
#define UNITS (B * (N / TILE))   // 2048

__device__ float g_xm[B * N];            // xm, overwritten in place with gate
__device__ int g_done[B];
__device__ volatile int g_flag[B];

// ---- K0: reset coordination state (determinism across graph replays) ----
__global__ void zero_kernel() {
    const int t = threadIdx.x;
    if (t < B) { g_done[t] = 0; g_flag[t] = 0; }
}

// ---- K1: fused per-unit max -> per-batch softmax -> per-unit scale ----
__global__ __launch_bounds__(256)
void fused_batchsync_kernel(const float* __restrict__ x, float* __restrict__ out) {
    __shared__ float pmax[4 * TILE];
    __shared__ float sred[8];
    __shared__ float s_scalar;
    __shared__ int   s_last;

    const int u  = blockIdx.x;           // unit
    const int b  = u >> 3;               // batch
    const int c0 = (u & 7) * TILE;       // column base
    const int t    = threadIdx.x;
    const int lane = t & 31;
    const int wid  = t >> 5;             // 8 warps

    const float* xb = x   + (size_t)b * (H * N) + c0;
    float*       ob = out + (size_t)b * (H * N) + c0;

    const int col4 = (t & 63) * 4;       // 0..252
    const int h0   = t >> 6;             // 0..3

    // ================= Phase A: column max over 64 rows =================
    float4 pm = make_float4(-INFINITY, -INFINITY, -INFINITY, -INFINITY);
    #pragma unroll
    for (int j = 0; j < 16; ++j) {
        const int h = h0 + j * 4;
        float4 v = *reinterpret_cast<const float4*>(xb + (size_t)h * N + col4);
        pm.x = fmaxf(pm.x, v.x);
        pm.y = fmaxf(pm.y, v.y);
        pm.z = fmaxf(pm.z, v.z);
        pm.w = fmaxf(pm.w, v.w);
    }
    *reinterpret_cast<float4*>(pmax + h0 * TILE + col4) = pm;
    __syncthreads();

    {   // thread t reduces column t of the tile, store xm
        float m = fmaxf(fmaxf(pmax[0 * TILE + t], pmax[1 * TILE + t]),
                        fmaxf(pmax[2 * TILE + t], pmax[3 * TILE + t]));
        g_xm[(size_t)b * N + c0 + t] = m;
    }
    __syncthreads();

    // ================= Arrive: last CTA of the batch does softmax =========
    if (t == 0) {
        __threadfence();                          // publish xm
        s_last = (atomicAdd(&g_done[b], 1) == 7);
    }
    __syncthreads();

    if (s_last) {
        // softmax over g_xm[b, :] (2048 floats, 8 per thread)
        float* row = g_xm + (size_t)b * N;
        float4 v0 = __ldcg(reinterpret_cast<const float4*>(row + t * 8));
        float4 v1 = __ldcg(reinterpret_cast<const float4*>(row + t * 8 + 4));

        float tm = fmaxf(fmaxf(fmaxf(v0.x, v0.y), fmaxf(v0.z, v0.w)),
                         fmaxf(fmaxf(v1.x, v1.y), fmaxf(v1.z, v1.w)));
        #pragma unroll
        for (int o = 16; o > 0; o >>= 1)
            tm = fmaxf(tm, __shfl_xor_sync(0xffffffffu, tm, o));
        if (lane == 0) sred[wid] = tm;
        __syncthreads();
        if (wid == 0) {
            float m = (lane < 8) ? sred[lane] : -INFINITY;
            #pragma unroll
            for (int o = 4; o > 0; o >>= 1)
                m = fmaxf(m, __shfl_xor_sync(0xffffffffu, m, o));
            if (lane == 0) s_scalar = m;
        }
        __syncthreads();
        const float gmax = s_scalar;
        __syncthreads();

        float4 e0, e1;
        e0.x = expf(v0.x - gmax); e0.y = expf(v0.y - gmax);
        e0.z = expf(v0.z - gmax); e0.w = expf(v0.w - gmax);
        e1.x = expf(v1.x - gmax); e1.y = expf(v1.y - gmax);
        e1.z = expf(v1.z - gmax); e1.w = expf(v1.w - gmax);
        float ts = ((e0.x + e0.y) + (e0.z + e0.w)) + ((e1.x + e1.y) + (e1.z + e1.w));
        #pragma unroll
        for (int o = 16; o > 0; o >>= 1)
            ts += __shfl_xor_sync(0xffffffffu, ts, o);
        if (lane == 0) sred[wid] = ts;
        __syncthreads();
        if (wid == 0) {
            float m = (lane < 8) ? sred[lane] : 0.0f;
            #pragma unroll
            for (int o = 4; o > 0; o >>= 1)
                m += __shfl_xor_sync(0xffffffffu, m, o);
            if (lane == 0) s_scalar = m;
        }
        __syncthreads();
        const float inv = 1.0f / s_scalar;

        e0.x *= inv; e0.y *= inv; e0.z *= inv; e0.w *= inv;
        e1.x *= inv; e1.y *= inv; e1.z *= inv; e1.w *= inv;
        *reinterpret_cast<float4*>(row + t * 8)     = e0;
        *reinterpret_cast<float4*>(row + t * 8 + 4) = e1;
        __syncthreads();
        if (t == 0) {
            __threadfence();                      // publish gate
            g_flag[b] = 1;
        }
    } else {
        if (t == 0) {
            while (g_flag[b] == 0) __nanosleep(200);
            __threadfence();                      // acquire
        }
    }
    __syncthreads();

    // ================= Phase C: out = gate * x ============================
    const float4 g4 = __ldcg(reinterpret_cast<const float4*>(
                         g_xm + (size_t)b * N + c0 + col4));
    #pragma unroll
    for (int j = 0; j < 16; ++j) {
        const int h = h0 + j * 4;
        float4 v = __ldcs(reinterpret_cast<const float4*>(xb + (size_t)h * N + col4));
        v.x *= g4.x; v.y *= g4.y; v.z *= g4.z; v.w *= g4.w;
        __stcs(reinterpret_cast<float4*>(ob + (size_t)h * N + col4), v);
    }
}

extern "C" void kernel_launch(void* const* d_in, const int* in_sizes, int n_in,
                              void* d_out, int out_size) {
    const float* x = (const float*)d_in[0];
    float* out = (float*)d_out;

    zero_kernel<<<1, 256>>>();
    fused_batchsync_kernel<<<UNITS, 256>>>(x, out);
}